// round 15
// baseline (speedup 1.0000x reference)
#include <cuda_runtime.h>
#include <cuda_bf16.h>
#include <cstdint>

// Shapes
#define M_TOTAL 10752          // B*T*N = 8*64*21
#define C_IN    128
#define F_OUT   256
#define N_SP    21
#define BM      128
#define MT      (M_TOTAL / BM) // 84 m-tiles
#define NCTA    (2 * MT)       // 168 CTAs <= 296 slots @2/SM -> single wave

// SMEM: A hi/lo (bf16, padded rows for conflict-free ldmatrix); Y reuses A.
#define TSTR    272
#define SM_AHI  0
#define SM_ALO  (SM_AHI + 128 * TSTR)     // 34816
#define SM_PS   (SM_ALO + 128 * TSTR)     // 69632
#define SM_PQ   (SM_PS + 1024)
#define SM_TOT  (SM_PQ + 1024)            // 71680 -> 2 CTAs/SM
#define YS      132                        // y staging stride (floats)

// Scratch (allocation-free device globals)
__device__ float g_psum[MT * F_OUT];
__device__ float g_psq [MT * F_OUT];
__device__ float g_scale[F_OUT];
__device__ float g_shift[F_OUT];
__device__ unsigned int g_ctr;
__device__ volatile unsigned int g_flag;
// W as per-lane mma B-fragments: [ft][wf][hl][ks][p][lane]
__device__ uint4 g_Bfrag[8192];              // 128 KB

__device__ __forceinline__ uint32_t smem_u32(const void* p) {
    uint32_t a;
    asm("{ .reg .u64 t; cvta.to.shared.u64 t, %1; cvt.u32.u64 %0, t; }"
        : "=r"(a) : "l"(p));
    return a;
}
__device__ __forceinline__ void ldsm4(uint32_t* r, uint32_t addr) {
    asm volatile("ldmatrix.sync.aligned.m8n8.x4.shared.b16 {%0,%1,%2,%3}, [%4];"
        : "=r"(r[0]), "=r"(r[1]), "=r"(r[2]), "=r"(r[3]) : "r"(addr));
}
__device__ __forceinline__ void mma16816(float* d, const uint32_t* a,
                                         uint32_t b0, uint32_t b1) {
    asm volatile("mma.sync.aligned.m16n8k16.row.col.f32.bf16.bf16.f32 "
        "{%0,%1,%2,%3}, {%4,%5,%6,%7}, {%8,%9}, {%0,%1,%2,%3};"
        : "+f"(d[0]), "+f"(d[1]), "+f"(d[2]), "+f"(d[3])
        : "r"(a[0]), "r"(a[1]), "r"(a[2]), "r"(a[3]), "r"(b0), "r"(b1));
}

// K0: split W into bf16 hi/lo mma B-fragments; reset ctr/flag (graph-replay safe)
__global__ __launch_bounds__(256) void wsplit_kernel(const float* __restrict__ W) {
    if (blockIdx.x == 0 && threadIdx.x == 0) { g_ctr = 0; g_flag = 0; }
    const int idx  = blockIdx.x * 256 + threadIdx.x;  // 0..8191
    const int lane = idx & 31;
    const int p    = (idx >> 5) & 3;
    const int ks   = (idx >> 7) & 7;
    const int hl   = (idx >> 10) & 1;
    const int wf   = (idx >> 11) & 1;
    const int ft   = (idx >> 12) & 1;
    const int F0 = ft * 128 + wf * 64 + p * 16 + (lane >> 2);
    const int k0 = ks * 16 + (lane & 3) * 2;

    auto elem = [&](int k, int f) -> __nv_bfloat16 {
        float v = W[k * F_OUT + f];
        __nv_bfloat16 h = __float2bfloat16(v);
        if (!hl) return h;
        return __float2bfloat16(v - __bfloat162float(h));
    };
    auto pk = [&](int k, int f) -> uint32_t {
        __nv_bfloat162 t; t.x = elem(k, f); t.y = elem(k + 1, f);
        return *(uint32_t*)&t;
    };
    uint4 r;
    r.x = pk(k0,     F0);
    r.y = pk(k0 + 8, F0);
    r.z = pk(k0,     F0 + 8);
    r.w = pk(k0 + 8, F0 + 8);
    g_Bfrag[idx] = r;
}

// K1: fully fused shift+GEMM+BN+ReLU. 128m x 128f per CTA; warp tile 32m x 64f
// (48 MMAs per ks-batch vs 12 loads). Single wave -> device barrier for BN.
__global__ __launch_bounds__(256, 2) void fused_kernel(const float* __restrict__ x,
                                                       const float* __restrict__ gamma,
                                                       const float* __restrict__ beta,
                                                       float* __restrict__ out) {
    extern __shared__ char smem[];
    const uint32_t sb = smem_u32(smem);
    const int tid   = threadIdx.x;
    const int ftile = blockIdx.x;            // 0..1
    const int mtile = blockIdx.y;            // 0..83
    const int m0    = mtile * BM;

    // ---- A: coalesced float4 load of 8 bt-groups (168 rows), shift on store ----
    {
        const int gs = m0 / N_SP;
        const float* xb = x + (size_t)gs * N_SP * C_IN;
        const int max_rl = M_TOTAL - gs * N_SP;      // rows available
        #pragma unroll
        for (int it = 0; it < 21; ++it) {
            const int idx = it * 256 + tid;          // 168*32 = 5376 chunks
            if (idx < 5376) {
                const int rl = idx >> 5;
                const int c4 = (idx & 31) * 4;
                if (rl < max_rl) {
                    float4 v = *(const float4*)&xb[rl * C_IN + c4];
                    const int g   = rl / N_SP;
                    const int inn = rl - g * N_SP;
                    const int bm  = (gs + g) * N_SP - m0;
                    const float vv[4] = { v.x, v.y, v.z, v.w };
                    #pragma unroll
                    for (int e = 0; e < 4; ++e) {
                        const int c = c4 + e;
                        int on = inn + c % N_SP;
                        if (on >= N_SP) on -= N_SP;
                        const int lm = bm + on;
                        if (lm >= 0 && lm < BM) {
                            float val = vv[e];
                            __nv_bfloat16 h = __float2bfloat16(val);
                            __nv_bfloat16 l = __float2bfloat16(val - __bfloat162float(h));
                            *(__nv_bfloat16*)(smem + SM_AHI + lm * TSTR + c * 2) = h;
                            *(__nv_bfloat16*)(smem + SM_ALO + lm * TSTR + c * 2) = l;
                        }
                    }
                }
            }
        }
    }
    __syncthreads();

    // ---- mainloop: A via ldmatrix (32m), B via direct global fragment loads ----
    const int lane = tid & 31, wid = tid >> 5;
    const int warp_m = wid & 3, warp_f = wid >> 2;   // 4 x 32m, 2 x 64f
    const int j = lane & 7, g = lane >> 3;
    const uint32_t abase = (uint32_t)((warp_m * 32 + j + ((g & 1) << 3)) * TSTR
                                      + (g >> 1) * 16);
    const uint32_t aHI0 = sb + SM_AHI + abase, aHI1 = aHI0 + 16 * TSTR;
    const uint32_t aLO0 = sb + SM_ALO + abase, aLO1 = aLO0 + 16 * TSTR;
    const uint4* BH = g_Bfrag + (ftile * 2 + warp_f) * 2048 + lane;
    const uint4* BL = BH + 1024;

    float acc[2][8][4];
    #pragma unroll
    for (int mh = 0; mh < 2; ++mh)
        #pragma unroll
        for (int a = 0; a < 8; ++a)
            #pragma unroll
            for (int e = 0; e < 4; ++e) acc[mh][a][e] = 0.f;

    #pragma unroll
    for (int ks = 0; ks < 8; ++ks) {
        uint32_t ah0[4], ah1[4], al0[4], al1[4];
        ldsm4(ah0, aHI0 + ks * 32);
        ldsm4(ah1, aHI1 + ks * 32);
        ldsm4(al0, aLO0 + ks * 32);
        ldsm4(al1, aLO1 + ks * 32);
        #pragma unroll
        for (int p = 0; p < 4; ++p) {
            const uint4 bh = __ldg(BH + (ks * 4 + p) * 32);
            const uint4 bl = __ldg(BL + (ks * 4 + p) * 32);
            mma16816(acc[0][p * 2],     ah0, bh.x, bh.y);   // hh
            mma16816(acc[0][p * 2 + 1], ah0, bh.z, bh.w);
            mma16816(acc[1][p * 2],     ah1, bh.x, bh.y);
            mma16816(acc[1][p * 2 + 1], ah1, bh.z, bh.w);
            mma16816(acc[0][p * 2],     ah0, bl.x, bl.y);   // hl
            mma16816(acc[0][p * 2 + 1], ah0, bl.z, bl.w);
            mma16816(acc[1][p * 2],     ah1, bl.x, bl.y);
            mma16816(acc[1][p * 2 + 1], ah1, bl.z, bl.w);
            mma16816(acc[0][p * 2],     al0, bh.x, bh.y);   // lh
            mma16816(acc[0][p * 2 + 1], al0, bh.z, bh.w);
            mma16816(acc[1][p * 2],     al1, bh.x, bh.y);
            mma16816(acc[1][p * 2 + 1], al1, bh.z, bh.w);
        }
    }
    __syncthreads();                          // A region dead -> reuse as Y

    // ---- stage y tile [128][YS] in smem; per-CTA BN partials -> global ----
    float* Y  = (float*)(smem + SM_AHI);
    float* Ps = (float*)(smem + SM_PS);
    float* Pq = (float*)(smem + SM_PQ);
    {
        const int rb = warp_m * 32 + (lane >> 2);
        #pragma unroll
        for (int mh = 0; mh < 2; ++mh)
            #pragma unroll
            for (int p = 0; p < 4; ++p)
                #pragma unroll
                for (int u = 0; u < 2; ++u) {
                    const int r0  = rb + mh * 16;
                    const int col = warp_f * 64 + p * 16 + u * 8 + (lane & 3) * 2;
                    float* d = acc[mh][p * 2 + u];
                    *(float2*)&Y[r0 * YS + col]       = make_float2(d[0], d[1]);
                    *(float2*)&Y[(r0 + 8) * YS + col] = make_float2(d[2], d[3]);
                }
    }
    __syncthreads();
    {
        const int part = tid >> 7, f = tid & 127;   // 2 parts x 64 rows
        float s = 0.f, q = 0.f;
        #pragma unroll 8
        for (int r = 0; r < 64; ++r) {
            float v = Y[(part * 64 + r) * YS + f];
            s += v; q += v * v;
        }
        Ps[part * 128 + f] = s;
        Pq[part * 128 + f] = q;
    }
    __syncthreads();
    if (tid < 128) {
        g_psum[mtile * F_OUT + ftile * 128 + tid] = Ps[tid] + Ps[128 + tid];
        g_psq [mtile * F_OUT + ftile * 128 + tid] = Pq[tid] + Pq[128 + tid];
    }
    __threadfence();
    __syncthreads();

    // ---- arrival; last CTA computes scale/shift and releases the flag ----
    __shared__ unsigned int s_last;
    if (tid == 0) s_last = (atomicAdd(&g_ctr, 1u) == NCTA - 1) ? 1u : 0u;
    __syncthreads();

    if (s_last) {
        const int f = tid;                    // 256 threads, one f each
        float s = 0.f, q = 0.f;
        #pragma unroll 12
        for (int t = 0; t < MT; ++t) {
            s += g_psum[t * F_OUT + f];
            q += g_psq [t * F_OUT + f];
        }
        const float inv = 1.0f / (float)M_TOTAL;
        float mean = s * inv;
        float var  = q * inv - mean * mean;
        float sc   = gamma[f] * rsqrtf(var + 1e-3f);
        g_scale[f] = sc;
        g_shift[f] = beta[f] - mean * sc;
        __threadfence();
        __syncthreads();
        if (tid == 0) g_flag = 1u;
    } else if (tid == 0) {
        while (g_flag == 0u) __nanosleep(64);
    }
    __syncthreads();
    __threadfence();

    // ---- stage this ftile's scale/shift, then normalize Y -> out ----
    if (tid < 128) {
        Ps[tid] = g_scale[ftile * 128 + tid];
        Pq[tid] = g_shift[ftile * 128 + tid];
    }
    __syncthreads();
    #pragma unroll
    for (int i = 0; i < 16; ++i) {
        const int id = i * 256 + tid;         // 128 rows x 32 f4 chunks
        const int r = id >> 5, c4 = (id & 31) * 4;
        float4 y = *(const float4*)&Y[r * YS + c4];
        float4 sc = *(const float4*)&Ps[c4];
        float4 sh = *(const float4*)&Pq[c4];
        float4 o;
        o.x = fmaxf(fmaf(y.x, sc.x, sh.x), 0.f);
        o.y = fmaxf(fmaf(y.y, sc.y, sh.y), 0.f);
        o.z = fmaxf(fmaf(y.z, sc.z, sh.z), 0.f);
        o.w = fmaxf(fmaf(y.w, sc.w, sh.w), 0.f);
        *(float4*)&out[(size_t)(m0 + r) * F_OUT + ftile * 128 + c4] = o;
    }
}

extern "C" void kernel_launch(void* const* d_in, const int* in_sizes, int n_in,
                              void* d_out, int out_size) {
    const float* x     = (const float*)d_in[0];
    const float* W     = (const float*)d_in[1];
    // d_in[2] = conv bias b: cancels exactly under BatchNorm -> unused
    const float* gamma = (const float*)d_in[3];
    const float* beta  = (const float*)d_in[4];

    cudaFuncSetAttribute(fused_kernel, cudaFuncAttributeMaxDynamicSharedMemorySize, SM_TOT);

    wsplit_kernel<<<32, 256>>>(W);
    fused_kernel<<<dim3(2, MT), 256, SM_TOT>>>(x, gamma, beta, (float*)d_out);
}

// round 16
// speedup vs baseline: 1.2010x; 1.2010x over previous
#include <cuda_runtime.h>
#include <cuda_bf16.h>
#include <cstdint>

// Shapes
#define M_TOTAL 10752          // B*T*N = 8*64*21
#define C_IN    128
#define F_OUT   256
#define N_SP    21
#define BM      64
#define MT      (M_TOTAL / BM) // 168 m-tiles

// SMEM: A hi/lo only (bf16, padded rows for conflict-free ldmatrix)
#define TSTR    272
#define SM_AHI  0
#define SM_ALO  (SM_AHI + 64 * TSTR)      // 17408
#define SM_PS   (SM_ALO + 64 * TSTR)      // 34816 (Y staging reuses A region)
#define SM_PQ   (SM_PS + 1024)
#define SM_TOT  (SM_PQ + 1024)            // 36864 -> 3 CTAs/SM
#define YS      132                        // y staging stride (floats)

// Scratch (allocation-free device globals)
__device__ float g_y[M_TOTAL * F_OUT];       // 11 MB pre-BN activations
__device__ float g_psum[MT * F_OUT];
__device__ float g_psq [MT * F_OUT];
__device__ float g_scale[F_OUT];
__device__ float g_shift[F_OUT];
// W as per-lane mma B-fragments: [ft][wf][hl][ks][p][lane]
__device__ uint4 g_Bfrag[8192];              // 128 KB, L1-resident

__device__ __forceinline__ uint32_t smem_u32(const void* p) {
    uint32_t a;
    asm("{ .reg .u64 t; cvta.to.shared.u64 t, %1; cvt.u32.u64 %0, t; }"
        : "=r"(a) : "l"(p));
    return a;
}
__device__ __forceinline__ void ldsm4(uint32_t* r, uint32_t addr) {
    asm volatile("ldmatrix.sync.aligned.m8n8.x4.shared.b16 {%0,%1,%2,%3}, [%4];"
        : "=r"(r[0]), "=r"(r[1]), "=r"(r[2]), "=r"(r[3]) : "r"(addr));
}
__device__ __forceinline__ void mma16816(float* d, const uint32_t* a,
                                         uint32_t b0, uint32_t b1) {
    asm volatile("mma.sync.aligned.m16n8k16.row.col.f32.bf16.bf16.f32 "
        "{%0,%1,%2,%3}, {%4,%5,%6,%7}, {%8,%9}, {%0,%1,%2,%3};"
        : "+f"(d[0]), "+f"(d[1]), "+f"(d[2]), "+f"(d[3])
        : "r"(a[0]), "r"(a[1]), "r"(a[2]), "r"(a[3]), "r"(b0), "r"(b1));
}

// K0: split W into bf16 hi/lo, stored directly as mma B-fragments per lane
__global__ __launch_bounds__(256) void wsplit_kernel(const float* __restrict__ W) {
    const int idx  = blockIdx.x * 256 + threadIdx.x;  // 0..8191
    const int lane = idx & 31;
    const int p    = (idx >> 5) & 3;
    const int ks   = (idx >> 7) & 7;
    const int hl   = (idx >> 10) & 1;
    const int wf   = (idx >> 11) & 1;
    const int ft   = (idx >> 12) & 1;
    const int F0 = ft * 128 + wf * 64 + p * 16 + (lane >> 2);
    const int k0 = ks * 16 + (lane & 3) * 2;

    auto elem = [&](int k, int f) -> __nv_bfloat16 {
        float v = W[k * F_OUT + f];
        __nv_bfloat16 h = __float2bfloat16(v);
        if (!hl) return h;
        return __float2bfloat16(v - __bfloat162float(h));
    };
    auto pk = [&](int k, int f) -> uint32_t {
        __nv_bfloat162 t; t.x = elem(k, f); t.y = elem(k + 1, f);
        return *(uint32_t*)&t;
    };
    uint4 r;
    r.x = pk(k0,     F0);
    r.y = pk(k0 + 8, F0);
    r.z = pk(k0,     F0 + 8);
    r.w = pk(k0 + 8, F0 + 8);
    g_Bfrag[idx] = r;
}

// K1: fused shift+GEMM (bf16x3 HMMA) -> y + BN partials (R8, proven)
__global__ __launch_bounds__(256, 3) void gemm_kernel(const float* __restrict__ x) {
    extern __shared__ char smem[];
    const uint32_t sb = smem_u32(smem);
    const int tid   = threadIdx.x;
    const int ftile = blockIdx.x;            // 0..1
    const int mtile = blockIdx.y;            // 0..167
    const int m0    = mtile * BM;

    // ---- A: coalesced float4 load of 4 whole bt-groups, shift on store ----
    {
        const int gs = m0 / N_SP;
        const float* xb = x + gs * N_SP * C_IN;
        #pragma unroll
        for (int it = 0; it < 11; ++it) {
            const int idx = it * 256 + tid;  // 84 rows * 32 float4 = 2688
            if (idx < 2688) {
                const int rl = idx >> 5;
                const int c4 = (idx & 31) * 4;
                float4 v = *(const float4*)&xb[rl * C_IN + c4];
                const int g   = rl / N_SP;
                const int inn = rl - g * N_SP;
                const int bm  = (gs + g) * N_SP - m0;
                const float vv[4] = { v.x, v.y, v.z, v.w };
                #pragma unroll
                for (int e = 0; e < 4; ++e) {
                    const int c = c4 + e;
                    int on = inn + c % N_SP;
                    if (on >= N_SP) on -= N_SP;
                    const int lm = bm + on;
                    if (lm >= 0 && lm < 64) {
                        float val = vv[e];
                        __nv_bfloat16 h = __float2bfloat16(val);
                        __nv_bfloat16 l = __float2bfloat16(val - __bfloat162float(h));
                        *(__nv_bfloat16*)(smem + SM_AHI + lm * TSTR + c * 2) = h;
                        *(__nv_bfloat16*)(smem + SM_ALO + lm * TSTR + c * 2) = l;
                    }
                }
            }
        }
    }
    __syncthreads();

    // ---- mainloop: A via ldmatrix, B via direct global fragment loads ----
    const int lane = tid & 31, wid = tid >> 5;
    const int warp_m = wid & 3, warp_f = wid >> 2;
    const int j = lane & 7, g = lane >> 3;
    const uint32_t aoff = (uint32_t)((warp_m * 16 + j + ((g & 1) << 3)) * TSTR
                                     + ((g >> 1) * 8) * 2);
    const uint32_t aHI = sb + SM_AHI + aoff, aLO = sb + SM_ALO + aoff;
    const uint4* BH = g_Bfrag + (ftile * 2 + warp_f) * 2048 + lane;
    const uint4* BL = BH + 1024;

    float acc[8][4];
    #pragma unroll
    for (int a = 0; a < 8; ++a)
        #pragma unroll
        for (int e = 0; e < 4; ++e) acc[a][e] = 0.f;

    #pragma unroll
    for (int ks = 0; ks < 8; ++ks) {
        uint32_t ah[4], al[4];
        ldsm4(ah, aHI + ks * 32);
        ldsm4(al, aLO + ks * 32);
        #pragma unroll
        for (int p = 0; p < 4; ++p) {
            const uint4 bh = __ldg(BH + (ks * 4 + p) * 32);
            const uint4 bl = __ldg(BL + (ks * 4 + p) * 32);
            mma16816(acc[p * 2],     ah, bh.x, bh.y);   // hh
            mma16816(acc[p * 2 + 1], ah, bh.z, bh.w);
            mma16816(acc[p * 2],     ah, bl.x, bl.y);   // hl
            mma16816(acc[p * 2 + 1], ah, bl.z, bl.w);
            mma16816(acc[p * 2],     al, bh.x, bh.y);   // lh
            mma16816(acc[p * 2 + 1], al, bh.z, bh.w);
        }
    }
    __syncthreads();                          // A region dead -> reuse as Y

    // ---- epilogue: stage y, BN partials, coalesced y store ----
    float* Y  = (float*)(smem + SM_AHI);      // [64][YS]
    float* Ps = (float*)(smem + SM_PS);
    float* Pq = (float*)(smem + SM_PQ);
    {
        const int r0 = warp_m * 16 + (lane >> 2);
        #pragma unroll
        for (int p = 0; p < 4; ++p)
            #pragma unroll
            for (int u = 0; u < 2; ++u) {
                const int col = warp_f * 64 + p * 16 + u * 8 + (lane & 3) * 2;
                float* d = acc[p * 2 + u];
                *(float2*)&Y[r0 * YS + col]       = make_float2(d[0], d[1]);
                *(float2*)&Y[(r0 + 8) * YS + col] = make_float2(d[2], d[3]);
            }
    }
    __syncthreads();
    {
        const int part = tid >> 7, f = tid & 127;   // 2 parts x 32 rows
        float s = 0.f, q = 0.f;
        #pragma unroll 8
        for (int r = 0; r < 32; ++r) {
            float v = Y[(part * 32 + r) * YS + f];
            s += v; q += v * v;
        }
        Ps[part * 128 + f] = s;
        Pq[part * 128 + f] = q;
    }
    // y store (coalesced float4): 64 rows x 32 chunks
    #pragma unroll
    for (int i = 0; i < 8; ++i) {
        const int id = i * 256 + tid;
        const int r = id >> 5, c4 = (id & 31) * 4;
        float4 v = *(const float4*)&Y[r * YS + c4];
        *(float4*)&g_y[(size_t)(m0 + r) * F_OUT + ftile * 128 + c4] = v;
    }
    __syncthreads();
    if (tid < 128) {
        g_psum[mtile * F_OUT + ftile * 128 + tid] = Ps[tid] + Ps[128 + tid];
        g_psq [mtile * F_OUT + ftile * 128 + tid] = Pq[tid] + Pq[128 + tid];
    }
}

// K2: finalize BN stats. One block per f (256 blocks): 168 parallel loads
// (single L2 latency round) + deterministic tree reduce.
__global__ __launch_bounds__(256) void stats_kernel(const float* __restrict__ gamma,
                                                    const float* __restrict__ beta) {
    __shared__ float ss[256], sq[256];
    const int f = blockIdx.x;
    const int t = threadIdx.x;
    float s = 0.f, q = 0.f;
    if (t < MT) {
        s = g_psum[t * F_OUT + f];
        q = g_psq [t * F_OUT + f];
    }
    ss[t] = s; sq[t] = q;
    __syncthreads();
    #pragma unroll
    for (int o = 128; o >= 32; o >>= 1) {
        if (t < o) { ss[t] += ss[t + o]; sq[t] += sq[t + o]; }
        __syncthreads();
    }
    if (t < 32) {
        float S = ss[t], Q = sq[t];
        #pragma unroll
        for (int o = 16; o > 0; o >>= 1) {
            S += __shfl_xor_sync(0xffffffffu, S, o);
            Q += __shfl_xor_sync(0xffffffffu, Q, o);
        }
        if (t == 0) {
            const float inv = 1.0f / (float)M_TOTAL;
            float mean = S * inv;
            float var  = Q * inv - mean * mean;
            float sc   = gamma[f] * rsqrtf(var + 1e-3f);
            g_scale[f] = sc;
            g_shift[f] = beta[f] - mean * sc;
        }
    }
}

// K3: normalize + relu. 1344 blocks x 256 threads, 2 float4/thread at +256
// stride (fb invariant -> one scale/shift load); high block count for spread.
__global__ __launch_bounds__(256) void norm_kernel(float* __restrict__ out) {
    const int base = blockIdx.x * 512 + threadIdx.x;   // float4 index
    const int fb = (base & 63) * 4;                    // same for both chunks
    float4 sc = *(const float4*)&g_scale[fb];
    float4 sh = *(const float4*)&g_shift[fb];

    float4 y0 = *(const float4*)&g_y[(size_t)base * 4];
    float4 y1 = *(const float4*)&g_y[(size_t)(base + 256) * 4];

    float4 o0, o1;
    o0.x = fmaxf(fmaf(y0.x, sc.x, sh.x), 0.f);
    o0.y = fmaxf(fmaf(y0.y, sc.y, sh.y), 0.f);
    o0.z = fmaxf(fmaf(y0.z, sc.z, sh.z), 0.f);
    o0.w = fmaxf(fmaf(y0.w, sc.w, sh.w), 0.f);
    o1.x = fmaxf(fmaf(y1.x, sc.x, sh.x), 0.f);
    o1.y = fmaxf(fmaf(y1.y, sc.y, sh.y), 0.f);
    o1.z = fmaxf(fmaf(y1.z, sc.z, sh.z), 0.f);
    o1.w = fmaxf(fmaf(y1.w, sc.w, sh.w), 0.f);
    *(float4*)&out[(size_t)base * 4]         = o0;
    *(float4*)&out[(size_t)(base + 256) * 4] = o1;
}

extern "C" void kernel_launch(void* const* d_in, const int* in_sizes, int n_in,
                              void* d_out, int out_size) {
    const float* x     = (const float*)d_in[0];
    const float* W     = (const float*)d_in[1];
    // d_in[2] = conv bias b: cancels exactly under BatchNorm -> unused
    const float* gamma = (const float*)d_in[3];
    const float* beta  = (const float*)d_in[4];

    cudaFuncSetAttribute(gemm_kernel, cudaFuncAttributeMaxDynamicSharedMemorySize, SM_TOT);

    wsplit_kernel<<<32, 256>>>(W);
    gemm_kernel<<<dim3(2, MT), 256, SM_TOT>>>(x);
    stats_kernel<<<256, 256>>>(gamma, beta);
    norm_kernel<<<(M_TOTAL * F_OUT) / (256 * 4 * 2), 256>>>((float*)d_out);
}